// round 5
// baseline (speedup 1.0000x reference)
#include <cuda_runtime.h>
#include <cuda_bf16.h>
#include <cstdint>

// Problem constants: B=32, S=2048, ENC=1024, DEC=1024
#define GB 32
#define GS 2048
#define GE 1024
#define GD 1024
#define GM (GB * GS)   // 65536 rows of enc_outputs

// -------- device scratch (allocation-free rule: __device__ globals) --------
__device__ float g_dec_proj[GB * GD];   // 128 KB
__device__ float g_scores[GB * GS];     // 256 KB

// ---------------------------------------------------------------------------
// Kernel 0: zero scores + context region of d_out (d_out is poisoned 0xAA)
// ---------------------------------------------------------------------------
__global__ void init_kernel(float* __restrict__ ctx) {
    int i = blockIdx.x * 256 + threadIdx.x;
    if (i < GB * GS) g_scores[i] = 0.0f;
    if (i < GB * GD) ctx[i] = 0.0f;
}

// ---------------------------------------------------------------------------
// Kernel 1: dec_proj[b,d] = sum_e dec_hidden[b,e] * attn_W[e,d] + attn_b[d]
// grid (8, 32), 128 threads; W_dec = first 1024 rows of attn_W
// ---------------------------------------------------------------------------
__global__ void dec_proj_kernel(const float* __restrict__ dec,
                                const float* __restrict__ W,
                                const float* __restrict__ bias) {
    __shared__ float sdec[GD];
    const int b  = blockIdx.y;
    const int d0 = blockIdx.x * 128;
    const int t  = threadIdx.x;

    for (int i = t; i < GD; i += 128) sdec[i] = dec[b * GD + i];
    __syncthreads();

    float acc = bias[d0 + t];
    const float* Wp = W + d0 + t;
#pragma unroll 8
    for (int e = 0; e < GD; e++)
        acc = fmaf(sdec[e], Wp[(size_t)e * GD], acc);
    g_dec_proj[b * GD + d0 + t] = acc;
}

// ---------------------------------------------------------------------------
// Kernel 2 (dominant, 137 GFLOP): fused
//   scores[r] += sum_{d in tile} tanh(enc[r,:] @ W_enc[:,d] + dec_proj[b,d]) * v[d]
// 128x128x16 SGEMM, 8x8 register microtile, double-buffered smem,
// register prefetch, fused tanh+v-dot epilogue with shfl reduce + atomicAdd.
// grid (512, 8) = (M/128, N/128), 256 threads.
// ---------------------------------------------------------------------------
__global__ __launch_bounds__(256, 2)
void scores_gemm_kernel(const float* __restrict__ A,    // enc_outputs [GM, GE]
                        const float* __restrict__ Bw,   // W_enc = attn_W + GD*GD, [GE, GD]
                        const float* __restrict__ vW)   // [GD]
{
    __shared__ float As[2][16][132];   // transposed A tile, +4 pad
    __shared__ float Bs[2][16][128];

    const int tid = threadIdx.x;
    const int tx  = tid & 15;          // col group (8 cols each)
    const int ty  = tid >> 4;          // row group (8 rows each)

    const int row0 = blockIdx.x * 128;
    const int col0 = blockIdx.y * 128;

    // global-load mapping
    const int a_row = tid >> 2;            // 0..63 (and +64)
    const int a_kc  = (tid & 3) << 2;      // k offset within tile: 0,4,8,12
    const int b_kr  = tid >> 5;            // 0..7 (and +8)
    const int b_c   = (tid & 31) << 2;     // 0..124

    const float* Aptr = A  + (size_t)row0 * GE;
    const float* Bptr = Bw + col0;

    float acc[8][8];
#pragma unroll
    for (int i = 0; i < 8; i++)
#pragma unroll
        for (int j = 0; j < 8; j++) acc[i][j] = 0.0f;

    // prefetch tile 0
    float4 ra0 = *(const float4*)(Aptr + (size_t)a_row        * GE + a_kc);
    float4 ra1 = *(const float4*)(Aptr + (size_t)(a_row + 64) * GE + a_kc);
    float4 rb0 = *(const float4*)(Bptr + (size_t)b_kr       * GD + b_c);
    float4 rb1 = *(const float4*)(Bptr + (size_t)(b_kr + 8) * GD + b_c);

    int buf = 0;
    As[buf][a_kc + 0][a_row] = ra0.x;
    As[buf][a_kc + 1][a_row] = ra0.y;
    As[buf][a_kc + 2][a_row] = ra0.z;
    As[buf][a_kc + 3][a_row] = ra0.w;
    As[buf][a_kc + 0][a_row + 64] = ra1.x;
    As[buf][a_kc + 1][a_row + 64] = ra1.y;
    As[buf][a_kc + 2][a_row + 64] = ra1.z;
    As[buf][a_kc + 3][a_row + 64] = ra1.w;
    *(float4*)&Bs[buf][b_kr][b_c]     = rb0;
    *(float4*)&Bs[buf][b_kr + 8][b_c] = rb1;
    __syncthreads();

    const int NT = GE / 16;   // 64 K-tiles
    for (int t = 0; t < NT; t++) {
        if (t + 1 < NT) {
            const int k0 = (t + 1) * 16;
            ra0 = *(const float4*)(Aptr + (size_t)a_row        * GE + k0 + a_kc);
            ra1 = *(const float4*)(Aptr + (size_t)(a_row + 64) * GE + k0 + a_kc);
            rb0 = *(const float4*)(Bptr + (size_t)(k0 + b_kr)     * GD + b_c);
            rb1 = *(const float4*)(Bptr + (size_t)(k0 + b_kr + 8) * GD + b_c);
        }
#pragma unroll
        for (int kk = 0; kk < 16; kk++) {
            float af[8], bf[8];
            *(float4*)&af[0] = *(const float4*)&As[buf][kk][ty * 8];
            *(float4*)&af[4] = *(const float4*)&As[buf][kk][ty * 8 + 4];
            *(float4*)&bf[0] = *(const float4*)&Bs[buf][kk][tx * 8];
            *(float4*)&bf[4] = *(const float4*)&Bs[buf][kk][tx * 8 + 4];
#pragma unroll
            for (int i = 0; i < 8; i++)
#pragma unroll
                for (int j = 0; j < 8; j++)
                    acc[i][j] = fmaf(af[i], bf[j], acc[i][j]);
        }
        if (t + 1 < NT) {
            const int nb = buf ^ 1;
            As[nb][a_kc + 0][a_row] = ra0.x;
            As[nb][a_kc + 1][a_row] = ra0.y;
            As[nb][a_kc + 2][a_row] = ra0.z;
            As[nb][a_kc + 3][a_row] = ra0.w;
            As[nb][a_kc + 0][a_row + 64] = ra1.x;
            As[nb][a_kc + 1][a_row + 64] = ra1.y;
            As[nb][a_kc + 2][a_row + 64] = ra1.z;
            As[nb][a_kc + 3][a_row + 64] = ra1.w;
            *(float4*)&Bs[nb][b_kr][b_c]     = rb0;
            *(float4*)&Bs[nb][b_kr + 8][b_c] = rb1;
            __syncthreads();
            buf = nb;
        }
    }

    // ---- fused epilogue: tanh(acc + dec_proj) * v, reduce over this N-tile ----
    const int b = row0 >> 11;       // 128 | 2048 -> single batch per row-tile
    float dp[8], vv[8];
#pragma unroll
    for (int j = 0; j < 8; j++) {
        dp[j] = g_dec_proj[b * GD + col0 + tx * 8 + j];
        vv[j] = vW[col0 + tx * 8 + j];
    }
#pragma unroll
    for (int i = 0; i < 8; i++) {
        float p = 0.0f;
#pragma unroll
        for (int j = 0; j < 8; j++)
            p = fmaf(tanhf(acc[i][j] + dp[j]), vv[j], p);
#pragma unroll
        for (int off = 8; off > 0; off >>= 1)
            p += __shfl_down_sync(0xffffffffu, p, off, 16);
        if (tx == 0)
            atomicAdd(&g_scores[row0 + ty * 8 + i], p);
    }
}

// ---------------------------------------------------------------------------
// Kernel 3: masked softmax over S per batch row. grid 32, 256 threads.
// MASK IS int32 (bool converted by harness): nonzero = keep.
// ---------------------------------------------------------------------------
__global__ void softmax_kernel(const int* __restrict__ mask,
                               float* __restrict__ attn) {
    __shared__ float sv[GS];
    __shared__ float red[8];
    const int b = blockIdx.x;
    const int t = threadIdx.x;

    float m = -3.4e38f;
    for (int s = t; s < GS; s += 256) {
        float v = g_scores[b * GS + s];
        v = (mask[b * GS + s] != 0) ? v : -10000.0f;
        sv[s] = v;
        m = fmaxf(m, v);
    }
#pragma unroll
    for (int off = 16; off > 0; off >>= 1)
        m = fmaxf(m, __shfl_xor_sync(0xffffffffu, m, off));
    if ((t & 31) == 0) red[t >> 5] = m;
    __syncthreads();
    if (t < 8) {
        float x = red[t];
#pragma unroll
        for (int off = 4; off > 0; off >>= 1)
            x = fmaxf(x, __shfl_xor_sync(0xffu, x, off));
        if (t == 0) red[0] = x;
    }
    __syncthreads();
    m = red[0];
    __syncthreads();

    float sum = 0.0f;
    for (int s = t; s < GS; s += 256) {
        float e = __expf(sv[s] - m);
        sv[s] = e;
        sum += e;
    }
#pragma unroll
    for (int off = 16; off > 0; off >>= 1)
        sum += __shfl_xor_sync(0xffffffffu, sum, off);
    if ((t & 31) == 0) red[t >> 5] = sum;
    __syncthreads();
    if (t < 8) {
        float x = red[t];
#pragma unroll
        for (int off = 4; off > 0; off >>= 1)
            x += __shfl_xor_sync(0xffu, x, off);
        if (t == 0) red[0] = x;
    }
    __syncthreads();
    const float inv = 1.0f / red[0];

    for (int s = t; s < GS; s += 256)
        attn[b * GS + s] = sv[s] * inv;
}

// ---------------------------------------------------------------------------
// Kernel 4: context[b,d] = sum_s attn[b,s] * enc[b,s,d]
// grid (16, 32): (s-chunk of 128, b). 256 threads, 4 d each. atomicAdd.
// ---------------------------------------------------------------------------
__global__ void context_kernel(const float* __restrict__ enc,
                               const float* __restrict__ attn,
                               float* __restrict__ ctx) {
    __shared__ float w[128];
    const int sc = blockIdx.x;
    const int b  = blockIdx.y;
    const int t  = threadIdx.x;

    if (t < 128) w[t] = attn[b * GS + sc * 128 + t];
    __syncthreads();

    const float* ep = enc + ((size_t)b * GS + sc * 128) * GE;
    float a0 = 0.f, a1 = 0.f, a2 = 0.f, a3 = 0.f;
#pragma unroll 4
    for (int s = 0; s < 128; s++) {
        const float ws = w[s];
        const float* p = ep + (size_t)s * GE + t;
        a0 = fmaf(ws, p[0],   a0);
        a1 = fmaf(ws, p[256], a1);
        a2 = fmaf(ws, p[512], a2);
        a3 = fmaf(ws, p[768], a3);
    }
    atomicAdd(&ctx[b * GD + t],       a0);
    atomicAdd(&ctx[b * GD + 256 + t], a1);
    atomicAdd(&ctx[b * GD + 512 + t], a2);
    atomicAdd(&ctx[b * GD + 768 + t], a3);
}

// ---------------------------------------------------------------------------
// kernel_launch.
// Inputs identified BY ELEMENT COUNT (robust to metadata ordering):
//   dec_hidden  32768, enc_outputs 67108864, src_mask 65536 (int32, bool-converted),
//   attn_W 2097152, attn_b 1024 (first 1024-sized), v_W 1024 (second 1024-sized)
// d_out: context [32,1024] then attn_w [32,2048]
// ---------------------------------------------------------------------------
extern "C" void kernel_launch(void* const* d_in, const int* in_sizes, int n_in,
                              void* d_out, int out_size) {
    const float* dec   = nullptr;
    const float* enc   = nullptr;
    const int*   mask  = nullptr;
    const float* attnW = nullptr;
    const float* attnB = nullptr;
    const float* vW    = nullptr;

    for (int i = 0; i < n_in; i++) {
        switch (in_sizes[i]) {
            case GM * GE:        enc   = (const float*)d_in[i]; break;  // 67108864
            case 2 * GD * GD:    attnW = (const float*)d_in[i]; break;  // 2097152
            case GB * GD:        dec   = (const float*)d_in[i]; break;  // 32768
            case GB * GS:        mask  = (const int*)d_in[i];   break;  // 65536
            case GD:                                                     // 1024 x2
                if (!attnB) attnB = (const float*)d_in[i];
                else        vW    = (const float*)d_in[i];
                break;
            default: break;
        }
    }

    float* ctx  = (float*)d_out;                 // [32,1024]
    float* attn = (float*)d_out + GB * GD;       // [32,2048]

    const float* Wenc = attnW + (size_t)GD * GD; // rows 1024..2047 = W_enc

    init_kernel<<<256, 256>>>(ctx);
    dec_proj_kernel<<<dim3(8, GB), 128>>>(dec, attnW, attnB);
    scores_gemm_kernel<<<dim3(GM / 128, GD / 128), 256>>>(enc, Wenc, vW);
    softmax_kernel<<<GB, 256>>>(mask, attn);
    context_kernel<<<dim3(GS / 128, GB), 256>>>(enc, attn, ctx);
}

// round 7
// speedup vs baseline: 1.8437x; 1.8437x over previous
#include <cuda_runtime.h>
#include <cuda_bf16.h>
#include <cstdint>

// Problem constants: B=32, S=2048, ENC=1024, DEC=1024
#define GB 32
#define GS 2048
#define GE 1024
#define GD 1024
#define GM (GB * GS)   // 65536 rows of enc_outputs

// -------- device scratch (allocation-free rule: __device__ globals) --------
__device__ float g_dec_proj[GB * GD];                         // 128 KB
__device__ float g_scores[GB * GS];                           // 256 KB
__device__ __align__(16) __nv_bfloat16 g_Bhi[GD * GE];        // 2 MB  W_enc^T hi
__device__ __align__(16) __nv_bfloat16 g_Blo[GD * GE];        // 2 MB  W_enc^T lo

__device__ __forceinline__ void bf16_split(float x, unsigned short& h, unsigned short& l) {
    __nv_bfloat16 hb = __float2bfloat16(x);          // RN
    float res = x - __bfloat162float(hb);            // exact in fp32
    __nv_bfloat16 lb = __float2bfloat16(res);
    h = __bfloat16_as_ushort(hb);
    l = __bfloat16_as_ushort(lb);
}

// m16n8k16 bf16 HMMA (baseline PTX, no 'a'-arch features)
#define MMA16816(C, A0, A1, A2, A3, B0, B1)                                   \
    asm volatile("mma.sync.aligned.m16n8k16.row.col.f32.bf16.bf16.f32 "       \
        "{%0,%1,%2,%3}, {%4,%5,%6,%7}, {%8,%9}, {%0,%1,%2,%3};"               \
        : "+f"((C)[0]), "+f"((C)[1]), "+f"((C)[2]), "+f"((C)[3])              \
        : "r"(A0), "r"(A1), "r"(A2), "r"(A3), "r"(B0), "r"(B1))

// ============================ small kernels ================================
__global__ void init_kernel(float* __restrict__ ctx) {
    int i = blockIdx.x * 256 + threadIdx.x;
    if (i < GB * GS) g_scores[i] = 0.0f;
    if (i < GB * GD) ctx[i] = 0.0f;
}

// W_enc [K=1024, N=1024] fp32 -> transposed bf16 hi/lo [N, K]
__global__ void prepB_kernel(const float* __restrict__ Wenc) {
    __shared__ float tile[32][33];
    const int kb = blockIdx.x << 5;
    const int nb = blockIdx.y << 5;
    const int tx = threadIdx.x;
    const int ty = threadIdx.y;
#pragma unroll
    for (int r = 0; r < 32; r += 8)
        tile[ty + r][tx] = Wenc[(size_t)(kb + ty + r) * GD + nb + tx];
    __syncthreads();
#pragma unroll
    for (int r = 0; r < 32; r += 8) {
        const int n = nb + ty + r;
        const int k = kb + tx;
        float x = tile[tx][ty + r];
        unsigned short h, l;
        bf16_split(x, h, l);
        g_Bhi[(size_t)n * GE + k] = __ushort_as_bfloat16(h);
        g_Blo[(size_t)n * GE + k] = __ushort_as_bfloat16(l);
    }
}

__global__ void dec_proj_kernel(const float* __restrict__ dec,
                                const float* __restrict__ W,
                                const float* __restrict__ bias) {
    __shared__ float sdec[GD];
    const int b  = blockIdx.y;
    const int d0 = blockIdx.x * 128;
    const int t  = threadIdx.x;
    for (int i = t; i < GD; i += 128) sdec[i] = dec[b * GD + i];
    __syncthreads();
    float acc = bias[d0 + t];
    const float* Wp = W + d0 + t;
#pragma unroll 8
    for (int e = 0; e < GD; e++)
        acc = fmaf(sdec[e], Wp[(size_t)e * GD], acc);
    g_dec_proj[b * GD + d0 + t] = acc;
}

// ====================== HMMA scores GEMM (dominant) ========================
// BM=128, BN=128, BK=32 bf16. 256 threads = 8 warps (4 m x 2 n), warp 32x64.
// 3 mma passes per fragment pair: Ah*Bh + Ah*Bl + Al*Bh (fp32 accumulate).
// A converted fp32->bf16 hi/lo on the fly; B pre-split in g_Bhi/g_Blo.
// Fused epilogue: tanh(acc + dec_proj)*v -> shfl reduce -> atomicAdd scores.
// grid = 4096 (N-tile fastest: 8 consecutive CTAs share the same A M-tile
// through L2). smem: double-buffered, padded stride 80B.

#define SKB 80                              // smem row stride bytes (40 bf16)
#define ABUF_SZ 10240                       // 128 rows * 80 B
#define SM_B0  40960                        // B region base
#define SM_DP  81920
#define SM_V   82432
#define GEMM_SMEM 83968

__global__ __launch_bounds__(256)
void scores_hmma_kernel(const float* __restrict__ A,     // enc [GM, GE]
                        const float* __restrict__ vW)    // [GD]
{
    extern __shared__ char sm[];
    const int tid  = threadIdx.x;
    const int wid  = tid >> 5;
    const int lane = tid & 31;
    const int grp  = lane >> 2;          // 0..7
    const int tig  = lane & 3;           // 0..3
    const int wm   = wid >> 1;           // 0..3  (m warp)
    const int wn   = wid & 1;            // 0..1  (n warp)

    const int nblk = blockIdx.x & 7;
    const int mblk = blockIdx.x >> 3;
    const int row0 = mblk << 7;
    const int col0 = nblk << 7;
    const int b    = mblk >> 4;          // batch (16 M-tiles per batch)

    float* dp_s = (float*)(sm + SM_DP);
    float* v_s  = (float*)(sm + SM_V);
    if (tid < 128) {
        dp_s[tid] = g_dec_proj[b * GD + col0 + tid];
        v_s[tid]  = vW[col0 + tid];
    }

    const float*         Aptr = A     + (size_t)row0 * GE;
    const __nv_bfloat16* bhp  = g_Bhi + (size_t)col0 * GE;
    const __nv_bfloat16* blp  = g_Blo + (size_t)col0 * GE;

    float acc[2][8][4];
#pragma unroll
    for (int mi = 0; mi < 2; mi++)
#pragma unroll
        for (int ni = 0; ni < 8; ni++)
#pragma unroll
            for (int j = 0; j < 4; j++) acc[mi][ni][j] = 0.0f;

    float4 pa[4];
    uint4  pb[4];

    // ---- global prefetch into registers (stage k0) ----
    auto gload = [&](int k0) {
#pragma unroll
        for (int i = 0; i < 4; i++) {
            const int c   = tid + (i << 8);
            const int row = c >> 3;
            const int kc  = (c & 7) << 2;
            pa[i] = *(const float4*)(Aptr + (size_t)row * GE + k0 + kc);
        }
#pragma unroll
        for (int i = 0; i < 4; i++) {
            const int c  = tid + (i << 8);
            const __nv_bfloat16* src = (c >> 9) ? blp : bhp;
            const int cc = c & 511;
            const int n  = cc >> 2;
            const int ke = (cc & 3) << 3;
            pb[i] = *(const uint4*)(src + (size_t)n * GE + k0 + ke);
        }
    };

    // ---- registers -> smem (convert A to hi/lo) ----
    auto sstore = [&](int buf) {
        char* sA = sm + buf * (2 * ABUF_SZ);
#pragma unroll
        for (int i = 0; i < 4; i++) {
            const int c   = tid + (i << 8);
            const int row = c >> 3;
            const int kc  = (c & 7) << 2;
            unsigned short h0, h1, h2, h3, l0, l1, l2, l3;
            bf16_split(pa[i].x, h0, l0);
            bf16_split(pa[i].y, h1, l1);
            bf16_split(pa[i].z, h2, l2);
            bf16_split(pa[i].w, h3, l3);
            uint2 uh, ul;
            uh.x = (uint32_t)h0 | ((uint32_t)h1 << 16);
            uh.y = (uint32_t)h2 | ((uint32_t)h3 << 16);
            ul.x = (uint32_t)l0 | ((uint32_t)l1 << 16);
            ul.y = (uint32_t)l2 | ((uint32_t)l3 << 16);
            *(uint2*)(sA + row * SKB + kc * 2)           = uh;
            *(uint2*)(sA + ABUF_SZ + row * SKB + kc * 2) = ul;
        }
        char* sB = sm + SM_B0 + buf * (2 * ABUF_SZ);
#pragma unroll
        for (int i = 0; i < 4; i++) {
            const int c   = tid + (i << 8);
            const int var = c >> 9;
            const int cc  = c & 511;
            const int n   = cc >> 2;
            const int ke  = (cc & 3) << 3;
            *(uint4*)(sB + var * ABUF_SZ + n * SKB + ke * 2) = pb[i];
        }
    };

    // ---- one BK=32 stage of HMMA (2 k16-steps x 3 passes) ----
    auto dostage = [&](int buf) {
        const char* sAh = sm + buf * (2 * ABUF_SZ);
        const char* sAl = sAh + ABUF_SZ;
        const char* sBh = sm + SM_B0 + buf * (2 * ABUF_SZ);
        const char* sBl = sBh + ABUF_SZ;
#pragma unroll
        for (int ks = 0; ks < 32; ks += 16) {
            const int kb = (ks + tig * 2) * 2;   // byte offset of this thread's k pair
            uint32_t aH[2][4], aL[2][4];
#pragma unroll
            for (int mi = 0; mi < 2; mi++) {
                const int r = wm * 32 + mi * 16 + grp;
                aH[mi][0] = *(const uint32_t*)(sAh + r * SKB + kb);
                aH[mi][1] = *(const uint32_t*)(sAh + (r + 8) * SKB + kb);
                aH[mi][2] = *(const uint32_t*)(sAh + r * SKB + kb + 16);
                aH[mi][3] = *(const uint32_t*)(sAh + (r + 8) * SKB + kb + 16);
                aL[mi][0] = *(const uint32_t*)(sAl + r * SKB + kb);
                aL[mi][1] = *(const uint32_t*)(sAl + (r + 8) * SKB + kb);
                aL[mi][2] = *(const uint32_t*)(sAl + r * SKB + kb + 16);
                aL[mi][3] = *(const uint32_t*)(sAl + (r + 8) * SKB + kb + 16);
            }
#pragma unroll
            for (int ni = 0; ni < 8; ni++) {
                const int n = wn * 64 + ni * 8 + grp;
                const uint32_t bh0 = *(const uint32_t*)(sBh + n * SKB + kb);
                const uint32_t bh1 = *(const uint32_t*)(sBh + n * SKB + kb + 16);
                const uint32_t bl0 = *(const uint32_t*)(sBl + n * SKB + kb);
                const uint32_t bl1 = *(const uint32_t*)(sBl + n * SKB + kb + 16);
#pragma unroll
                for (int mi = 0; mi < 2; mi++) {
                    MMA16816(acc[mi][ni], aH[mi][0], aH[mi][1], aH[mi][2], aH[mi][3], bh0, bh1);
                    MMA16816(acc[mi][ni], aH[mi][0], aH[mi][1], aH[mi][2], aH[mi][3], bl0, bl1);
                    MMA16816(acc[mi][ni], aL[mi][0], aL[mi][1], aL[mi][2], aL[mi][3], bh0, bh1);
                }
            }
        }
    };

    gload(0);
    sstore(0);
    __syncthreads();

    for (int t = 0; t < 32; t++) {
        const int buf = t & 1;
        if (t < 31) gload((t + 1) << 5);
        dostage(buf);
        if (t < 31) {
            sstore(buf ^ 1);   // safe: buf^1 last read at iter t-1, synced since
            __syncthreads();
        }
    }

    // ---- fused epilogue: tanh(acc + dec_proj) * v, reduce, atomicAdd ------
    float rp[4] = {0.f, 0.f, 0.f, 0.f};
#pragma unroll
    for (int mi = 0; mi < 2; mi++)
#pragma unroll
        for (int ni = 0; ni < 8; ni++) {
            const int cl = wn * 64 + ni * 8 + tig * 2;
            const float d0 = dp_s[cl],     v0 = v_s[cl];
            const float d1 = dp_s[cl + 1], v1 = v_s[cl + 1];
            rp[mi * 2 + 0] += tanhf(acc[mi][ni][0] + d0) * v0
                            + tanhf(acc[mi][ni][1] + d1) * v1;
            rp[mi * 2 + 1] += tanhf(acc[mi][ni][2] + d0) * v0
                            + tanhf(acc[mi][ni][3] + d1) * v1;
        }
#pragma unroll
    for (int j = 0; j < 4; j++) {
        rp[j] += __shfl_xor_sync(0xffffffffu, rp[j], 1);
        rp[j] += __shfl_xor_sync(0xffffffffu, rp[j], 2);
    }
    if (tig == 0) {
        const int rbase = row0 + wm * 32 + grp;
        atomicAdd(&g_scores[rbase],      rp[0]);
        atomicAdd(&g_scores[rbase + 8],  rp[1]);
        atomicAdd(&g_scores[rbase + 16], rp[2]);
        atomicAdd(&g_scores[rbase + 24], rp[3]);
    }
}

// ============================ softmax + context ============================
__global__ void softmax_kernel(const int* __restrict__ mask,
                               float* __restrict__ attn) {
    __shared__ float sv[GS];
    __shared__ float red[8];
    const int b = blockIdx.x;
    const int t = threadIdx.x;

    float m = -3.4e38f;
    for (int s = t; s < GS; s += 256) {
        float v = g_scores[b * GS + s];
        v = (mask[b * GS + s] != 0) ? v : -10000.0f;
        sv[s] = v;
        m = fmaxf(m, v);
    }
#pragma unroll
    for (int off = 16; off > 0; off >>= 1)
        m = fmaxf(m, __shfl_xor_sync(0xffffffffu, m, off));
    if ((t & 31) == 0) red[t >> 5] = m;
    __syncthreads();
    if (t < 8) {
        float x = red[t];
#pragma unroll
        for (int off = 4; off > 0; off >>= 1)
            x = fmaxf(x, __shfl_xor_sync(0xffu, x, off));
        if (t == 0) red[0] = x;
    }
    __syncthreads();
    m = red[0];
    __syncthreads();

    float sum = 0.0f;
    for (int s = t; s < GS; s += 256) {
        float e = __expf(sv[s] - m);
        sv[s] = e;
        sum += e;
    }
#pragma unroll
    for (int off = 16; off > 0; off >>= 1)
        sum += __shfl_xor_sync(0xffffffffu, sum, off);
    if ((t & 31) == 0) red[t >> 5] = sum;
    __syncthreads();
    if (t < 8) {
        float x = red[t];
#pragma unroll
        for (int off = 4; off > 0; off >>= 1)
            x += __shfl_xor_sync(0xffu, x, off);
        if (t == 0) red[0] = x;
    }
    __syncthreads();
    const float inv = 1.0f / red[0];

    for (int s = t; s < GS; s += 256)
        attn[b * GS + s] = sv[s] * inv;
}

__global__ void context_kernel(const float* __restrict__ enc,
                               const float* __restrict__ attn,
                               float* __restrict__ ctx) {
    __shared__ float w[128];
    const int sc = blockIdx.x;
    const int b  = blockIdx.y;
    const int t  = threadIdx.x;

    if (t < 128) w[t] = attn[b * GS + sc * 128 + t];
    __syncthreads();

    const float* ep = enc + ((size_t)b * GS + sc * 128) * GE;
    float a0 = 0.f, a1 = 0.f, a2 = 0.f, a3 = 0.f;
#pragma unroll 4
    for (int s = 0; s < 128; s++) {
        const float ws = w[s];
        const float* p = ep + (size_t)s * GE + t;
        a0 = fmaf(ws, p[0],   a0);
        a1 = fmaf(ws, p[256], a1);
        a2 = fmaf(ws, p[512], a2);
        a3 = fmaf(ws, p[768], a3);
    }
    atomicAdd(&ctx[b * GD + t],       a0);
    atomicAdd(&ctx[b * GD + 256 + t], a1);
    atomicAdd(&ctx[b * GD + 512 + t], a2);
    atomicAdd(&ctx[b * GD + 768 + t], a3);
}

// ============================ kernel_launch ================================
// Inputs identified BY ELEMENT COUNT (robust to ordering):
//   enc 67108864, attn_W 2097152, dec 32768, mask 65536 (int32, bool-conv),
//   attn_b / v_W both 1024 (keep relative order).
extern "C" void kernel_launch(void* const* d_in, const int* in_sizes, int n_in,
                              void* d_out, int out_size) {
    const float* dec   = nullptr;
    const float* enc   = nullptr;
    const int*   mask  = nullptr;
    const float* attnW = nullptr;
    const float* attnB = nullptr;
    const float* vW    = nullptr;

    for (int i = 0; i < n_in; i++) {
        switch (in_sizes[i]) {
            case GM * GE:     enc   = (const float*)d_in[i]; break;
            case 2 * GD * GD: attnW = (const float*)d_in[i]; break;
            case GB * GD:     dec   = (const float*)d_in[i]; break;
            case GB * GS:     mask  = (const int*)d_in[i];   break;
            case GD:
                if (!attnB) attnB = (const float*)d_in[i];
                else        vW    = (const float*)d_in[i];
                break;
            default: break;
        }
    }

    float* ctx  = (float*)d_out;             // [32,1024]
    float* attn = (float*)d_out + GB * GD;   // [32,2048]

    const float* Wenc = attnW + (size_t)GD * GD;   // rows 1024..2047

    cudaFuncSetAttribute(scores_hmma_kernel,
                         cudaFuncAttributeMaxDynamicSharedMemorySize,
                         GEMM_SMEM);

    init_kernel<<<256, 256>>>(ctx);
    prepB_kernel<<<dim3(GE / 32, GD / 32), dim3(32, 8)>>>(Wenc);
    dec_proj_kernel<<<dim3(8, GB), 128>>>(dec, attnW, attnB);
    scores_hmma_kernel<<<(GM / 128) * (GD / 128), 256, GEMM_SMEM>>>(enc, vW);
    softmax_kernel<<<GB, 256>>>(mask, attn);
    context_kernel<<<dim3(GS / 128, GB), 256>>>(enc, attn, ctx);
}

// round 8
// speedup vs baseline: 1.9789x; 1.0733x over previous
#include <cuda_runtime.h>
#include <cuda_bf16.h>
#include <cstdint>

// Problem constants: B=32, S=2048, ENC=1024, DEC=1024
#define GB 32
#define GS 2048
#define GE 1024
#define GD 1024
#define GM (GB * GS)   // 65536 rows of enc_outputs

// -------- device scratch (allocation-free rule: __device__ globals) --------
__device__ float g_dec_proj[GB * GD];                         // 128 KB
__device__ float g_scores[GB * GS];                           // 256 KB
__device__ __align__(16) __nv_bfloat16 g_Bhi[GD * GE];        // 2 MB  W_enc^T hi
__device__ __align__(16) __nv_bfloat16 g_Blo[GD * GE];        // 2 MB  W_enc^T lo

__device__ __forceinline__ void bf16_split(float x, unsigned short& h, unsigned short& l) {
    __nv_bfloat16 hb = __float2bfloat16(x);          // RN
    float res = x - __bfloat162float(hb);            // exact in fp32
    __nv_bfloat16 lb = __float2bfloat16(res);
    h = __bfloat16_as_ushort(hb);
    l = __bfloat16_as_ushort(lb);
}

// m16n8k16 bf16 HMMA (baseline PTX)
#define MMA16816(C, A0, A1, A2, A3, B0, B1)                                   \
    asm volatile("mma.sync.aligned.m16n8k16.row.col.f32.bf16.bf16.f32 "       \
        "{%0,%1,%2,%3}, {%4,%5,%6,%7}, {%8,%9}, {%0,%1,%2,%3};"               \
        : "+f"((C)[0]), "+f"((C)[1]), "+f"((C)[2]), "+f"((C)[3])              \
        : "r"(A0), "r"(A1), "r"(A2), "r"(A3), "r"(B0), "r"(B1))

#define LDSM_X4(R, addr)                                                      \
    asm volatile("ldmatrix.sync.aligned.m8n8.x4.shared.b16 {%0,%1,%2,%3}, [%4];" \
        : "=r"((R)[0]), "=r"((R)[1]), "=r"((R)[2]), "=r"((R)[3]) : "r"(addr))

#define CP_ASYNC16(saddr, gptr)                                               \
    asm volatile("cp.async.cg.shared.global [%0], [%1], 16;"                  \
        :: "r"(saddr), "l"(gptr) : "memory")
#define CP_COMMIT()  asm volatile("cp.async.commit_group;" ::: "memory")
#define CP_WAIT0()   asm volatile("cp.async.wait_group 0;" ::: "memory")

__device__ __forceinline__ uint32_t smem_u32(const void* p) {
    uint32_t a;
    asm("{ .reg .u64 t; cvta.to.shared.u64 t, %1; cvt.u32.u64 %0, t; }"
        : "=r"(a) : "l"(p));
    return a;
}

// ============================ small kernels ================================
__global__ void init_kernel(float* __restrict__ ctx) {
    int i = blockIdx.x * 256 + threadIdx.x;
    if (i < GB * GS) g_scores[i] = 0.0f;
    if (i < GB * GD) ctx[i] = 0.0f;
}

// W_enc [K=1024, N=1024] fp32 -> transposed bf16 hi/lo [N, K]
__global__ void prepB_kernel(const float* __restrict__ Wenc) {
    __shared__ float tile[32][33];
    const int kb = blockIdx.x << 5;
    const int nb = blockIdx.y << 5;
    const int tx = threadIdx.x;
    const int ty = threadIdx.y;
#pragma unroll
    for (int r = 0; r < 32; r += 8)
        tile[ty + r][tx] = Wenc[(size_t)(kb + ty + r) * GD + nb + tx];
    __syncthreads();
#pragma unroll
    for (int r = 0; r < 32; r += 8) {
        const int n = nb + ty + r;
        const int k = kb + tx;
        float x = tile[tx][ty + r];
        unsigned short h, l;
        bf16_split(x, h, l);
        g_Bhi[(size_t)n * GE + k] = __ushort_as_bfloat16(h);
        g_Blo[(size_t)n * GE + k] = __ushort_as_bfloat16(l);
    }
}

__global__ void dec_proj_kernel(const float* __restrict__ dec,
                                const float* __restrict__ W,
                                const float* __restrict__ bias) {
    __shared__ float sdec[GD];
    const int b  = blockIdx.y;
    const int d0 = blockIdx.x * 128;
    const int t  = threadIdx.x;
    for (int i = t; i < GD; i += 128) sdec[i] = dec[b * GD + i];
    __syncthreads();
    float acc = bias[d0 + t];
    const float* Wp = W + d0 + t;
#pragma unroll 8
    for (int e = 0; e < GD; e++)
        acc = fmaf(sdec[e], Wp[(size_t)e * GD], acc);
    g_dec_proj[b * GD + d0 + t] = acc;
}

// ====================== HMMA scores GEMM (dominant) ========================
// BM=128, BN=128, BK=32. 512 threads = 16 warps (4m x 4n), warp tile 32x32.
// 3 mma passes: Ah*Bh + Ah*Bl + Al*Bh. A converted fp32->bf16 hi/lo in regs;
// B (pre-split) staged via cp.async.cg. Fragments via ldmatrix.x4 from
// 80B-stride smem (conflict-free LDSM). Double buffer, 1 sync per stage.
// Fused epilogue: tanh(acc+dec_proj)*v -> shfl reduce -> atomicAdd scores.

#define SKB   80                            // smem row stride bytes (40 bf16)
#define VBUF  10240                         // 128 rows * 80 B (one variant)
#define BUFST 20480                         // hi+lo for one buffer
#define SM_B0 40960                         // B region base
#define SM_DP 81920
#define SM_V  82432
#define GEMM_SMEM 83968

__global__ __launch_bounds__(512, 1)
void scores_hmma_kernel(const float* __restrict__ A,     // enc [GM, GE]
                        const float* __restrict__ vW)    // [GD]
{
    extern __shared__ char sm[];
    const uint32_t sm_u = smem_u32(sm);
    const int tid  = threadIdx.x;
    const int wid  = tid >> 5;
    const int lane = tid & 31;
    const int grp  = lane >> 2;          // 0..7
    const int tig  = lane & 3;           // 0..3
    const int wm   = wid >> 2;           // 0..3  (m warp)
    const int wn   = wid & 3;            // 0..3  (n warp)
    const int m8   = lane >> 3;          // ldmatrix matrix id 0..3
    const int ri   = lane & 7;           // ldmatrix row-in-matrix

    const int nblk = blockIdx.x & 7;
    const int mblk = blockIdx.x >> 3;
    const int row0 = mblk << 7;
    const int col0 = nblk << 7;
    const int b    = mblk >> 4;          // batch (16 M-tiles per batch)

    float* dp_s = (float*)(sm + SM_DP);
    float* v_s  = (float*)(sm + SM_V);
    if (tid < 128) {
        dp_s[tid] = g_dec_proj[b * GD + col0 + tid];
        v_s[tid]  = vW[col0 + tid];
    }

    const float*         Aptr = A     + (size_t)row0 * GE;
    const __nv_bfloat16* bhp  = g_Bhi + (size_t)col0 * GE;
    const __nv_bfloat16* blp  = g_Blo + (size_t)col0 * GE;

    float acc[2][4][4];
#pragma unroll
    for (int mi = 0; mi < 2; mi++)
#pragma unroll
        for (int ni = 0; ni < 4; ni++)
#pragma unroll
            for (int j = 0; j < 4; j++) acc[mi][ni][j] = 0.0f;

    // per-thread A global-load mapping (2 float4 per stage)
    const int a_row0 = tid >> 3;             // c = tid
    const int a_kc0  = (tid & 7) << 2;
    const int a_row1 = (tid + 512) >> 3;     // c = tid + 512
    const int a_kc1  = (tid & 7) << 2;       // same k phase

    // per-thread B cp.async mapping (2 chunks per stage)
    const int  bvar0 = tid >> 9;             // 0 for tid<512 -> always 0
    const int  bcc0  = tid & 511;
    const int  bn0   = bcc0 >> 2;
    const int  bch0  = bcc0 & 3;
    const int  bcc1  = (tid + 512) & 511;
    const int  bn1   = bcc1 >> 2;
    const int  bch1  = bcc1 & 3;
    // chunk 0 -> var 0 (hi), chunk 1 -> var 1 (lo)
    const uint32_t bs0 = sm_u + SM_B0 + bn0 * SKB + bch0 * 16;            // + var0*VBUF(=0)
    const uint32_t bs1 = sm_u + SM_B0 + VBUF + bn1 * SKB + bch1 * 16;     // var 1
    const __nv_bfloat16* bg0 = bhp + (size_t)bn0 * GE + bch0 * 8;
    const __nv_bfloat16* bg1 = blp + (size_t)bn1 * GE + bch1 * 8;
    (void)bvar0;

    // ldmatrix base addresses (A: rows=m, B: rows=n), matrix-id dependent
    const uint32_t aLd = sm_u + (wm * 32 + (m8 & 1) * 8 + ri) * SKB + (m8 >> 1) * 16;
    const uint32_t bLd = sm_u + SM_B0 + (wn * 32 + (m8 >> 1) * 8 + ri) * SKB + (m8 & 1) * 16;

    float4 pa[2];

    auto gloadA = [&](int k0) {
        pa[0] = *(const float4*)(Aptr + (size_t)a_row0 * GE + k0 + a_kc0);
        pa[1] = *(const float4*)(Aptr + (size_t)a_row1 * GE + k0 + a_kc1);
    };
    auto cpB = [&](int k0, int buf) {
        CP_ASYNC16(bs0 + buf * BUFST, (const void*)(bg0 + k0));
        CP_ASYNC16(bs1 + buf * BUFST, (const void*)(bg1 + k0));
    };
    auto sstoreA = [&](int buf) {
        char* base = sm + buf * BUFST;
#pragma unroll
        for (int i = 0; i < 2; i++) {
            const int row = i ? a_row1 : a_row0;
            const int kc  = i ? a_kc1  : a_kc0;
            unsigned short h0, h1, h2, h3, l0, l1, l2, l3;
            bf16_split(pa[i].x, h0, l0);
            bf16_split(pa[i].y, h1, l1);
            bf16_split(pa[i].z, h2, l2);
            bf16_split(pa[i].w, h3, l3);
            uint2 uh, ul;
            uh.x = (uint32_t)h0 | ((uint32_t)h1 << 16);
            uh.y = (uint32_t)h2 | ((uint32_t)h3 << 16);
            ul.x = (uint32_t)l0 | ((uint32_t)l1 << 16);
            ul.y = (uint32_t)l2 | ((uint32_t)l3 << 16);
            *(uint2*)(base + row * SKB + kc * 2)        = uh;
            *(uint2*)(base + VBUF + row * SKB + kc * 2) = ul;
        }
    };

    auto dostage = [&](int buf) {
        const uint32_t aB = aLd + buf * BUFST;
        const uint32_t bB = bLd + buf * BUFST;
#pragma unroll
        for (int ks = 0; ks < 2; ks++) {
            const uint32_t ko = ks * 32;
            uint32_t aH[2][4], aL[2][4];
            LDSM_X4(aH[0], aB + ko);
            LDSM_X4(aH[1], aB + 1280 + ko);          // mi=1: +16 rows
            LDSM_X4(aL[0], aB + VBUF + ko);
            LDSM_X4(aL[1], aB + VBUF + 1280 + ko);
            uint32_t bH[2][4], bL[2][4];
            LDSM_X4(bH[0], bB + ko);
            LDSM_X4(bH[1], bB + 1280 + ko);          // nipair=1: +16 n
            LDSM_X4(bL[0], bB + VBUF + ko);
            LDSM_X4(bL[1], bB + VBUF + 1280 + ko);
#pragma unroll
            for (int np = 0; np < 2; np++)
#pragma unroll
                for (int sub = 0; sub < 2; sub++) {
                    const int ni = np * 2 + sub;
                    const uint32_t bh0 = bH[np][sub * 2], bh1 = bH[np][sub * 2 + 1];
                    const uint32_t bl0 = bL[np][sub * 2], bl1 = bL[np][sub * 2 + 1];
#pragma unroll
                    for (int mi = 0; mi < 2; mi++) {
                        MMA16816(acc[mi][ni], aH[mi][0], aH[mi][1], aH[mi][2], aH[mi][3], bh0, bh1);
                        MMA16816(acc[mi][ni], aH[mi][0], aH[mi][1], aH[mi][2], aH[mi][3], bl0, bl1);
                        MMA16816(acc[mi][ni], aL[mi][0], aL[mi][1], aL[mi][2], aL[mi][3], bh0, bh1);
                    }
                }
        }
    };

    gloadA(0);
    cpB(0, 0);
    CP_COMMIT();
    sstoreA(0);
    CP_WAIT0();
    __syncthreads();

    for (int t = 0; t < 32; t++) {
        const int buf = t & 1;
        if (t < 31) {
            gloadA((t + 1) << 5);
            cpB((t + 1) << 5, buf ^ 1);
            CP_COMMIT();
        }
        dostage(buf);
        if (t < 31) {
            sstoreA(buf ^ 1);
            CP_WAIT0();
            __syncthreads();
        }
    }

    // ---- fused epilogue: tanh(acc + dec_proj) * v, reduce, atomicAdd ------
    float rp[4] = {0.f, 0.f, 0.f, 0.f};
#pragma unroll
    for (int mi = 0; mi < 2; mi++)
#pragma unroll
        for (int ni = 0; ni < 4; ni++) {
            const int cl = wn * 32 + ni * 8 + tig * 2;
            const float d0 = dp_s[cl],     v0 = v_s[cl];
            const float d1 = dp_s[cl + 1], v1 = v_s[cl + 1];
            rp[mi * 2 + 0] += tanhf(acc[mi][ni][0] + d0) * v0
                            + tanhf(acc[mi][ni][1] + d1) * v1;
            rp[mi * 2 + 1] += tanhf(acc[mi][ni][2] + d0) * v0
                            + tanhf(acc[mi][ni][3] + d1) * v1;
        }
#pragma unroll
    for (int j = 0; j < 4; j++) {
        rp[j] += __shfl_xor_sync(0xffffffffu, rp[j], 1);
        rp[j] += __shfl_xor_sync(0xffffffffu, rp[j], 2);
    }
    if (tig == 0) {
        const int rbase = row0 + wm * 32 + grp;
        atomicAdd(&g_scores[rbase],      rp[0]);   // mi=0, row grp
        atomicAdd(&g_scores[rbase + 8],  rp[1]);   // mi=0, row grp+8
        atomicAdd(&g_scores[rbase + 16], rp[2]);   // mi=1, row grp
        atomicAdd(&g_scores[rbase + 24], rp[3]);   // mi=1, row grp+8
    }
}

// ============================ softmax + context ============================
__global__ void softmax_kernel(const int* __restrict__ mask,
                               float* __restrict__ attn) {
    __shared__ float sv[GS];
    __shared__ float red[8];
    const int b = blockIdx.x;
    const int t = threadIdx.x;

    float m = -3.4e38f;
    for (int s = t; s < GS; s += 256) {
        float v = g_scores[b * GS + s];
        v = (mask[b * GS + s] != 0) ? v : -10000.0f;
        sv[s] = v;
        m = fmaxf(m, v);
    }
#pragma unroll
    for (int off = 16; off > 0; off >>= 1)
        m = fmaxf(m, __shfl_xor_sync(0xffffffffu, m, off));
    if ((t & 31) == 0) red[t >> 5] = m;
    __syncthreads();
    if (t < 8) {
        float x = red[t];
#pragma unroll
        for (int off = 4; off > 0; off >>= 1)
            x = fmaxf(x, __shfl_xor_sync(0xffu, x, off));
        if (t == 0) red[0] = x;
    }
    __syncthreads();
    m = red[0];
    __syncthreads();

    float sum = 0.0f;
    for (int s = t; s < GS; s += 256) {
        float e = __expf(sv[s] - m);
        sv[s] = e;
        sum += e;
    }
#pragma unroll
    for (int off = 16; off > 0; off >>= 1)
        sum += __shfl_xor_sync(0xffffffffu, sum, off);
    if ((t & 31) == 0) red[t >> 5] = sum;
    __syncthreads();
    if (t < 8) {
        float x = red[t];
#pragma unroll
        for (int off = 4; off > 0; off >>= 1)
            x += __shfl_xor_sync(0xffu, x, off);
        if (t == 0) red[0] = x;
    }
    __syncthreads();
    const float inv = 1.0f / red[0];

    for (int s = t; s < GS; s += 256)
        attn[b * GS + s] = sv[s] * inv;
}

__global__ void context_kernel(const float* __restrict__ enc,
                               const float* __restrict__ attn,
                               float* __restrict__ ctx) {
    __shared__ float w[128];
    const int sc = blockIdx.x;
    const int b  = blockIdx.y;
    const int t  = threadIdx.x;

    if (t < 128) w[t] = attn[b * GS + sc * 128 + t];
    __syncthreads();

    const float* ep = enc + ((size_t)b * GS + sc * 128) * GE;
    float a0 = 0.f, a1 = 0.f, a2 = 0.f, a3 = 0.f;
#pragma unroll 4
    for (int s = 0; s < 128; s++) {
        const float ws = w[s];
        const float* p = ep + (size_t)s * GE + t;
        a0 = fmaf(ws, p[0],   a0);
        a1 = fmaf(ws, p[256], a1);
        a2 = fmaf(ws, p[512], a2);
        a3 = fmaf(ws, p[768], a3);
    }
    atomicAdd(&ctx[b * GD + t],       a0);
    atomicAdd(&ctx[b * GD + 256 + t], a1);
    atomicAdd(&ctx[b * GD + 512 + t], a2);
    atomicAdd(&ctx[b * GD + 768 + t], a3);
}

// ============================ kernel_launch ================================
// Inputs identified BY ELEMENT COUNT (robust to ordering):
//   enc 67108864, attn_W 2097152, dec 32768, mask 65536 (int32, bool-conv),
//   attn_b / v_W both 1024 (keep relative order).
extern "C" void kernel_launch(void* const* d_in, const int* in_sizes, int n_in,
                              void* d_out, int out_size) {
    const float* dec   = nullptr;
    const float* enc   = nullptr;
    const int*   mask  = nullptr;
    const float* attnW = nullptr;
    const float* attnB = nullptr;
    const float* vW    = nullptr;

    for (int i = 0; i < n_in; i++) {
        switch (in_sizes[i]) {
            case GM * GE:     enc   = (const float*)d_in[i]; break;
            case 2 * GD * GD: attnW = (const float*)d_in[i]; break;
            case GB * GD:     dec   = (const float*)d_in[i]; break;
            case GB * GS:     mask  = (const int*)d_in[i];   break;
            case GD:
                if (!attnB) attnB = (const float*)d_in[i];
                else        vW    = (const float*)d_in[i];
                break;
            default: break;
        }
    }

    float* ctx  = (float*)d_out;             // [32,1024]
    float* attn = (float*)d_out + GB * GD;   // [32,2048]

    const float* Wenc = attnW + (size_t)GD * GD;   // rows 1024..2047

    cudaFuncSetAttribute(scores_hmma_kernel,
                         cudaFuncAttributeMaxDynamicSharedMemorySize,
                         GEMM_SMEM);

    init_kernel<<<256, 256>>>(ctx);
    prepB_kernel<<<dim3(GE / 32, GD / 32), dim3(32, 8)>>>(Wenc);
    dec_proj_kernel<<<dim3(8, GB), 128>>>(dec, attnW, attnB);
    scores_hmma_kernel<<<(GM / 128) * (GD / 128), 512, GEMM_SMEM>>>(enc, vW);
    softmax_kernel<<<GB, 256>>>(mask, attn);
    context_kernel<<<dim3(GS / 128, GB), 256>>>(enc, attn, ctx);
}

// round 9
// speedup vs baseline: 2.2355x; 1.1297x over previous
#include <cuda_runtime.h>
#include <cuda_bf16.h>
#include <cstdint>

// Problem constants: B=32, S=2048, ENC=1024, DEC=1024
#define GB 32
#define GS 2048
#define GE 1024
#define GD 1024
#define GM (GB * GS)   // 65536 rows of enc_outputs

// -------- device scratch (allocation-free rule: __device__ globals) --------
__device__ float g_dec_proj[GB * GD];                         // 128 KB
__device__ float g_scores[GB * GS];                           // 256 KB
__device__ __align__(16) __nv_bfloat16 g_Bhi[GD * GE];        // 2 MB   W_enc^T hi
__device__ __align__(16) __nv_bfloat16 g_Blo[GD * GE];        // 2 MB   W_enc^T lo
__device__ __align__(16) __nv_bfloat16 g_Ahi[(size_t)GM * GE]; // 128 MB enc hi
__device__ __align__(16) __nv_bfloat16 g_Alo[(size_t)GM * GE]; // 128 MB enc lo

__device__ __forceinline__ void bf16_split(float x, unsigned short& h, unsigned short& l) {
    __nv_bfloat16 hb = __float2bfloat16(x);          // RN
    float res = x - __bfloat162float(hb);
    __nv_bfloat16 lb = __float2bfloat16(res);
    h = __bfloat16_as_ushort(hb);
    l = __bfloat16_as_ushort(lb);
}

// m16n8k16 bf16 HMMA (baseline PTX)
#define MMA16816(C, A0, A1, A2, A3, B0, B1)                                   \
    asm volatile("mma.sync.aligned.m16n8k16.row.col.f32.bf16.bf16.f32 "       \
        "{%0,%1,%2,%3}, {%4,%5,%6,%7}, {%8,%9}, {%0,%1,%2,%3};"               \
        : "+f"((C)[0]), "+f"((C)[1]), "+f"((C)[2]), "+f"((C)[3])              \
        : "r"(A0), "r"(A1), "r"(A2), "r"(A3), "r"(B0), "r"(B1))

#define LDSM_X4(R, addr)                                                      \
    asm volatile("ldmatrix.sync.aligned.m8n8.x4.shared.b16 {%0,%1,%2,%3}, [%4];" \
        : "=r"((R)[0]), "=r"((R)[1]), "=r"((R)[2]), "=r"((R)[3]) : "r"(addr))

#define CP_ASYNC16(saddr, gptr)                                               \
    asm volatile("cp.async.cg.shared.global [%0], [%1], 16;"                  \
        :: "r"(saddr), "l"(gptr) : "memory")
#define CP_COMMIT()  asm volatile("cp.async.commit_group;" ::: "memory")
#define CP_WAIT1()   asm volatile("cp.async.wait_group 1;" ::: "memory")

__device__ __forceinline__ uint32_t smem_u32(const void* p) {
    uint32_t a;
    asm("{ .reg .u64 t; cvta.to.shared.u64 t, %1; cvt.u32.u64 %0, t; }"
        : "=r"(a) : "l"(p));
    return a;
}

// ============================ small kernels ================================
__global__ void init_kernel(float* __restrict__ ctx) {
    int i = blockIdx.x * 256 + threadIdx.x;
    if (i < GB * GS) g_scores[i] = 0.0f;
    if (i < GB * GD) ctx[i] = 0.0f;
}

// enc [GM, GE] fp32 -> bf16 hi/lo, same layout. 32768 blocks x 512 thr x 1 float4.
__global__ __launch_bounds__(512)
void prepA_kernel(const float* __restrict__ enc) {
    const size_t i = ((size_t)blockIdx.x * 512 + threadIdx.x) * 4;
    float4 f = *(const float4*)(enc + i);
    unsigned short h0, h1, h2, h3, l0, l1, l2, l3;
    bf16_split(f.x, h0, l0); bf16_split(f.y, h1, l1);
    bf16_split(f.z, h2, l2); bf16_split(f.w, h3, l3);
    uint2 uh, ul;
    uh.x = (uint32_t)h0 | ((uint32_t)h1 << 16);
    uh.y = (uint32_t)h2 | ((uint32_t)h3 << 16);
    ul.x = (uint32_t)l0 | ((uint32_t)l1 << 16);
    ul.y = (uint32_t)l2 | ((uint32_t)l3 << 16);
    *(uint2*)((char*)g_Ahi + i * 2) = uh;
    *(uint2*)((char*)g_Alo + i * 2) = ul;
}

// W_enc [K=1024, N=1024] fp32 -> transposed bf16 hi/lo [N, K]
__global__ void prepB_kernel(const float* __restrict__ Wenc) {
    __shared__ float tile[32][33];
    const int kb = blockIdx.x << 5;
    const int nb = blockIdx.y << 5;
    const int tx = threadIdx.x;
    const int ty = threadIdx.y;
#pragma unroll
    for (int r = 0; r < 32; r += 8)
        tile[ty + r][tx] = Wenc[(size_t)(kb + ty + r) * GD + nb + tx];
    __syncthreads();
#pragma unroll
    for (int r = 0; r < 32; r += 8) {
        const int n = nb + ty + r;
        const int k = kb + tx;
        float x = tile[tx][ty + r];
        unsigned short h, l;
        bf16_split(x, h, l);
        g_Bhi[(size_t)n * GE + k] = __ushort_as_bfloat16(h);
        g_Blo[(size_t)n * GE + k] = __ushort_as_bfloat16(l);
    }
}

__global__ void dec_proj_kernel(const float* __restrict__ dec,
                                const float* __restrict__ W,
                                const float* __restrict__ bias) {
    __shared__ float sdec[GD];
    const int b  = blockIdx.y;
    const int d0 = blockIdx.x * 128;
    const int t  = threadIdx.x;
    for (int i = t; i < GD; i += 128) sdec[i] = dec[b * GD + i];
    __syncthreads();
    float acc = bias[d0 + t];
    const float* Wp = W + d0 + t;
#pragma unroll 8
    for (int e = 0; e < GD; e++)
        acc = fmaf(sdec[e], Wp[(size_t)e * GD], acc);
    g_dec_proj[b * GD + d0 + t] = acc;
}

// ====================== HMMA scores GEMM (dominant) ========================
// BM=128, BN=128, BK=32. 512 threads = 16 warps (4m x 4n), warp tile 32x32.
// 3 mma passes: Ah*Bh + Ah*Bl + Al*Bh. ALL tiles (A pre-split by prepA, B by
// prepB) arrive via cp.async 3-stage circular pipeline; no register staging.
// Fragments: ldmatrix.x4 from 80B-stride smem, double-buffered across ksteps.
// Fused epilogue: tanh(acc+dec_proj)*v -> shfl reduce -> atomicAdd scores.

#define SKB    80                           // smem row stride bytes (40 bf16)
#define REG_SZ 10240                        // one region: 128 rows * 80 B
#define STG_SZ 40960                        // Ah | Al | Bh | Bl
#define NSTG   3
#define SM_DP  (NSTG * STG_SZ)              // 122880
#define SM_V   (SM_DP + 512)
#define GEMM_SMEM (SM_V + 512)              // 123904

__global__ __launch_bounds__(512, 1)
void scores_hmma_kernel(const float* __restrict__ vW)    // [GD]
{
    extern __shared__ char sm[];
    const uint32_t sm_u = smem_u32(sm);
    const int tid  = threadIdx.x;
    const int wid  = tid >> 5;
    const int lane = tid & 31;
    const int grp  = lane >> 2;          // 0..7
    const int tig  = lane & 3;           // 0..3
    const int wm   = wid >> 2;           // 0..3  (m warp)
    const int wn   = wid & 3;            // 0..3  (n warp)
    const int m8   = lane >> 3;          // ldmatrix matrix id 0..3
    const int ri   = lane & 7;           // ldmatrix row-in-matrix

    const int nblk = blockIdx.x & 7;
    const int mblk = blockIdx.x >> 3;
    const int row0 = mblk << 7;
    const int col0 = nblk << 7;
    const int b    = mblk >> 4;          // batch (16 M-tiles per batch)

    float* dp_s = (float*)(sm + SM_DP);
    float* v_s  = (float*)(sm + SM_V);
    if (tid < 128) {
        dp_s[tid] = g_dec_proj[b * GD + col0 + tid];
        v_s[tid]  = vW[col0 + tid];
    }

    // ---- cp.async mapping: each thread moves 1x16B per region per stage ---
    const int cprow = tid >> 2;              // 0..127
    const int cpch  = tid & 3;               // 16B chunk in 64B row
    const uint32_t sdst = sm_u + cprow * SKB + cpch * 16;
    const __nv_bfloat16* gAh = g_Ahi + (size_t)(row0 + cprow) * GE + cpch * 8;
    const __nv_bfloat16* gAl = g_Alo + (size_t)(row0 + cprow) * GE + cpch * 8;
    const __nv_bfloat16* gBh = g_Bhi + (size_t)(col0 + cprow) * GE + cpch * 8;
    const __nv_bfloat16* gBl = g_Blo + (size_t)(col0 + cprow) * GE + cpch * 8;

    auto issue_cp = [&](int stg, int k0) {
        const uint32_t d = sdst + stg * STG_SZ;
        CP_ASYNC16(d,              (const void*)(gAh + k0));
        CP_ASYNC16(d + REG_SZ,     (const void*)(gAl + k0));
        CP_ASYNC16(d + 2 * REG_SZ, (const void*)(gBh + k0));
        CP_ASYNC16(d + 3 * REG_SZ, (const void*)(gBl + k0));
    };

    // ---- ldmatrix base addresses ----
    const uint32_t aLd = sm_u + (wm * 32 + (m8 & 1) * 8 + ri) * SKB + (m8 >> 1) * 16;
    const uint32_t bLd = sm_u + 2 * REG_SZ +
                         (wn * 32 + (m8 >> 1) * 8 + ri) * SKB + (m8 & 1) * 16;

    float acc[2][4][4];
#pragma unroll
    for (int mi = 0; mi < 2; mi++)
#pragma unroll
        for (int ni = 0; ni < 4; ni++)
#pragma unroll
            for (int j = 0; j < 4; j++) acc[mi][ni][j] = 0.0f;

    uint32_t aH[2][2][4], aL[2][2][4], bH[2][2][4], bL[2][2][4]; // [fbuf][mi/np][4]

    auto ldfrags = [&](int fb, uint32_t aB, uint32_t bB, int ks) {
        const uint32_t ko = ks * 32;
        LDSM_X4(aH[fb][0], aB + ko);
        LDSM_X4(aH[fb][1], aB + 1280 + ko);            // +16 rows
        LDSM_X4(aL[fb][0], aB + REG_SZ + ko);
        LDSM_X4(aL[fb][1], aB + REG_SZ + 1280 + ko);
        LDSM_X4(bH[fb][0], bB + ko);
        LDSM_X4(bH[fb][1], bB + 1280 + ko);            // +16 n
        LDSM_X4(bL[fb][0], bB + REG_SZ + ko);
        LDSM_X4(bL[fb][1], bB + REG_SZ + 1280 + ko);
    };
    auto domma = [&](int fb) {
#pragma unroll
        for (int np = 0; np < 2; np++)
#pragma unroll
            for (int sub = 0; sub < 2; sub++) {
                const int ni = np * 2 + sub;
                const uint32_t bh0 = bH[fb][np][sub * 2], bh1 = bH[fb][np][sub * 2 + 1];
                const uint32_t bl0 = bL[fb][np][sub * 2], bl1 = bL[fb][np][sub * 2 + 1];
#pragma unroll
                for (int mi = 0; mi < 2; mi++) {
                    MMA16816(acc[mi][ni], aH[fb][mi][0], aH[fb][mi][1], aH[fb][mi][2], aH[fb][mi][3], bh0, bh1);
                    MMA16816(acc[mi][ni], aH[fb][mi][0], aH[fb][mi][1], aH[fb][mi][2], aH[fb][mi][3], bl0, bl1);
                    MMA16816(acc[mi][ni], aL[fb][mi][0], aL[fb][mi][1], aL[fb][mi][2], aL[fb][mi][3], bh0, bh1);
                }
            }
    };

    // ---- prologue: 2 stages in flight ----
    issue_cp(0, 0);  CP_COMMIT();
    issue_cp(1, 32); CP_COMMIT();

    int stg = 0;
    for (int t = 0; t < 32; t++) {
        CP_WAIT1();                        // stage t data resident
        __syncthreads();
        const uint32_t aB = aLd + stg * STG_SZ;
        const uint32_t bB = bLd + stg * STG_SZ;
        ldfrags(0, aB, bB, 0);             // kstep 0 fragments
        if (t + 2 < 32) {
            int ns = stg + 2; if (ns >= NSTG) ns -= NSTG;
            issue_cp(ns, (t + 2) << 5);
        }
        CP_COMMIT();                       // one group per iteration (may be empty)
        ldfrags(1, aB, bB, 1);             // kstep 1 fragments (overlaps kstep 0 MMA)
        domma(0);
        domma(1);
        if (++stg == NSTG) stg = 0;
    }

    // ---- fused epilogue: tanh(acc + dec_proj) * v, reduce, atomicAdd ------
    float rp[4] = {0.f, 0.f, 0.f, 0.f};
#pragma unroll
    for (int mi = 0; mi < 2; mi++)
#pragma unroll
        for (int ni = 0; ni < 4; ni++) {
            const int cl = wn * 32 + ni * 8 + tig * 2;
            const float d0 = dp_s[cl],     v0 = v_s[cl];
            const float d1 = dp_s[cl + 1], v1 = v_s[cl + 1];
            rp[mi * 2 + 0] += tanhf(acc[mi][ni][0] + d0) * v0
                            + tanhf(acc[mi][ni][1] + d1) * v1;
            rp[mi * 2 + 1] += tanhf(acc[mi][ni][2] + d0) * v0
                            + tanhf(acc[mi][ni][3] + d1) * v1;
        }
#pragma unroll
    for (int j = 0; j < 4; j++) {
        rp[j] += __shfl_xor_sync(0xffffffffu, rp[j], 1);
        rp[j] += __shfl_xor_sync(0xffffffffu, rp[j], 2);
    }
    if (tig == 0) {
        const int rbase = row0 + wm * 32 + grp;
        atomicAdd(&g_scores[rbase],      rp[0]);
        atomicAdd(&g_scores[rbase + 8],  rp[1]);
        atomicAdd(&g_scores[rbase + 16], rp[2]);
        atomicAdd(&g_scores[rbase + 24], rp[3]);
    }
}

// ============================ softmax + context ============================
__global__ void softmax_kernel(const int* __restrict__ mask,
                               float* __restrict__ attn) {
    __shared__ float sv[GS];
    __shared__ float red[8];
    const int b = blockIdx.x;
    const int t = threadIdx.x;

    float m = -3.4e38f;
    for (int s = t; s < GS; s += 256) {
        float v = g_scores[b * GS + s];
        v = (mask[b * GS + s] != 0) ? v : -10000.0f;
        sv[s] = v;
        m = fmaxf(m, v);
    }
#pragma unroll
    for (int off = 16; off > 0; off >>= 1)
        m = fmaxf(m, __shfl_xor_sync(0xffffffffu, m, off));
    if ((t & 31) == 0) red[t >> 5] = m;
    __syncthreads();
    if (t < 8) {
        float x = red[t];
#pragma unroll
        for (int off = 4; off > 0; off >>= 1)
            x = fmaxf(x, __shfl_xor_sync(0xffu, x, off));
        if (t == 0) red[0] = x;
    }
    __syncthreads();
    m = red[0];
    __syncthreads();

    float sum = 0.0f;
    for (int s = t; s < GS; s += 256) {
        float e = __expf(sv[s] - m);
        sv[s] = e;
        sum += e;
    }
#pragma unroll
    for (int off = 16; off > 0; off >>= 1)
        sum += __shfl_xor_sync(0xffffffffu, sum, off);
    if ((t & 31) == 0) red[t >> 5] = sum;
    __syncthreads();
    if (t < 8) {
        float x = red[t];
#pragma unroll
        for (int off = 4; off > 0; off >>= 1)
            x += __shfl_xor_sync(0xffu, x, off);
        if (t == 0) red[0] = x;
    }
    __syncthreads();
    const float inv = 1.0f / red[0];

    for (int s = t; s < GS; s += 256)
        attn[b * GS + s] = sv[s] * inv;
}

__global__ void context_kernel(const float* __restrict__ enc,
                               const float* __restrict__ attn,
                               float* __restrict__ ctx) {
    __shared__ float w[128];
    const int sc = blockIdx.x;
    const int b  = blockIdx.y;
    const int t  = threadIdx.x;

    if (t < 128) w[t] = attn[b * GS + sc * 128 + t];
    __syncthreads();

    const float* ep = enc + ((size_t)b * GS + sc * 128) * GE;
    float a0 = 0.f, a1 = 0.f, a2 = 0.f, a3 = 0.f;
#pragma unroll 4
    for (int s = 0; s < 128; s++) {
        const float ws = w[s];
        const float* p = ep + (size_t)s * GE + t;
        a0 = fmaf(ws, p[0],   a0);
        a1 = fmaf(ws, p[256], a1);
        a2 = fmaf(ws, p[512], a2);
        a3 = fmaf(ws, p[768], a3);
    }
    atomicAdd(&ctx[b * GD + t],       a0);
    atomicAdd(&ctx[b * GD + 256 + t], a1);
    atomicAdd(&ctx[b * GD + 512 + t], a2);
    atomicAdd(&ctx[b * GD + 768 + t], a3);
}

// ============================ kernel_launch ================================
// Inputs identified BY ELEMENT COUNT (robust to ordering):
//   enc 67108864, attn_W 2097152, dec 32768, mask 65536 (int32, bool-conv),
//   attn_b / v_W both 1024 (keep relative order).
extern "C" void kernel_launch(void* const* d_in, const int* in_sizes, int n_in,
                              void* d_out, int out_size) {
    const float* dec   = nullptr;
    const float* enc   = nullptr;
    const int*   mask  = nullptr;
    const float* attnW = nullptr;
    const float* attnB = nullptr;
    const float* vW    = nullptr;

    for (int i = 0; i < n_in; i++) {
        switch (in_sizes[i]) {
            case GM * GE:     enc   = (const float*)d_in[i]; break;
            case 2 * GD * GD: attnW = (const float*)d_in[i]; break;
            case GB * GD:     dec   = (const float*)d_in[i]; break;
            case GB * GS:     mask  = (const int*)d_in[i];   break;
            case GD:
                if (!attnB) attnB = (const float*)d_in[i];
                else        vW    = (const float*)d_in[i];
                break;
            default: break;
        }
    }

    float* ctx  = (float*)d_out;             // [32,1024]
    float* attn = (float*)d_out + GB * GD;   // [32,2048]

    const float* Wenc = attnW + (size_t)GD * GD;   // rows 1024..2047

    cudaFuncSetAttribute(scores_hmma_kernel,
                         cudaFuncAttributeMaxDynamicSharedMemorySize,
                         GEMM_SMEM);

    init_kernel<<<256, 256>>>(ctx);
    prepA_kernel<<<GM * (GE / 4) / 512, 512>>>(enc);
    prepB_kernel<<<dim3(GE / 32, GD / 32), dim3(32, 8)>>>(Wenc);
    dec_proj_kernel<<<dim3(8, GB), 128>>>(dec, attnW, attnB);
    scores_hmma_kernel<<<(GM / 128) * (GD / 128), 512, GEMM_SMEM>>>(vW);
    softmax_kernel<<<GB, 256>>>(mask, attn);
    context_kernel<<<dim3(GS / 128, GB), 256>>>(enc, attn, ctx);
}